// round 2
// baseline (speedup 1.0000x reference)
#include <cuda_runtime.h>

#define N_NODES 100000
#define N_EDGES 1600000
#define DIM 128

// Scratch (allocation-free rule: __device__ globals)
__device__ float g_xw[(size_t)N_NODES * DIM];   // 51.2 MB
__device__ float g_dis[N_NODES];
__device__ int   g_deg[N_NODES];
__device__ int   g_row[N_EDGES];
__device__ int   g_col[N_EDGES];
__device__ int   g_orflag;   // OR of odd int32 words; 0 => edge_index is int64

// ---------------- dtype detect + convert ----------------
__global__ void k_zero_flag() { g_orflag = 0; }

__global__ void k_detect(const int* __restrict__ ei32) {
    // Reads only the first 2*N_EDGES int32 words (safe for both int32 and int64 layouts).
    int i = blockIdx.x * blockDim.x + threadIdx.x;
    int acc = 0;
    // each thread checks a strided set of odd words
    for (int j = i; j < N_EDGES; j += gridDim.x * blockDim.x)
        acc |= ei32[2 * j + 1];
    if (acc != 0) atomicOr(&g_orflag, 1);
}

__global__ void k_convert(const int* __restrict__ ei32) {
    int e = blockIdx.x * blockDim.x + threadIdx.x;
    if (e >= N_EDGES) return;
    if (g_orflag == 0) {
        // int64 layout: [row int64 x E][col int64 x E]; take low words
        g_row[e] = ei32[2 * e];
        g_col[e] = ei32[2 * (N_EDGES + e)];
    } else {
        // int32 layout: [row int32 x E][col int32 x E]
        g_row[e] = ei32[e];
        g_col[e] = ei32[N_EDGES + e];
    }
}

// ---------------- degree / norm ----------------
__global__ void k_zero_deg() {
    int i = blockIdx.x * blockDim.x + threadIdx.x;
    if (i < N_NODES) g_deg[i] = 0;
}

__global__ void k_hist() {
    int e = blockIdx.x * blockDim.x + threadIdx.x;
    if (e < N_EDGES) atomicAdd(&g_deg[g_col[e]], 1);
}

__global__ void k_dis() {
    int i = blockIdx.x * blockDim.x + threadIdx.x;
    if (i < N_NODES) g_dis[i] = rsqrtf((float)(g_deg[i] + 1)); // +1 self loop
}

// ---------------- GEMM: xw = x @ W, epilogue writes out = xw * dis^2 ----------------
// BM=64, BN=128 (full), BK=32. 256 threads, per-thread 4x8 microtile.
__global__ __launch_bounds__(256) void k_gemm(const float* __restrict__ x,
                                              const float* __restrict__ W,
                                              float* __restrict__ out) {
    __shared__ float As[64][33];
    __shared__ float Bs[32][128];
    const int m0  = blockIdx.x * 64;
    const int tid = threadIdx.x;
    const int tr  = tid >> 4;   // 0..15
    const int tc  = tid & 15;   // 0..15

    float acc[4][8];
#pragma unroll
    for (int i = 0; i < 4; i++)
#pragma unroll
        for (int j = 0; j < 8; j++) acc[i][j] = 0.f;

    for (int kt = 0; kt < DIM; kt += 32) {
#pragma unroll
        for (int i = 0; i < 8; i++) {
            int idx = tid + i * 256;
            int r = idx >> 5, c = idx & 31;
            int gr = m0 + r;
            As[r][c] = (gr < N_NODES) ? x[(size_t)gr * DIM + kt + c] : 0.f;
        }
#pragma unroll
        for (int i = 0; i < 16; i++) {
            int idx = tid + i * 256;
            int r = idx >> 7, c = idx & 127;
            Bs[r][c] = W[(kt + r) * DIM + c];
        }
        __syncthreads();
#pragma unroll
        for (int k = 0; k < 32; k++) {
            float a[4], b[8];
#pragma unroll
            for (int i = 0; i < 4; i++) a[i] = As[tr * 4 + i][k];
#pragma unroll
            for (int j = 0; j < 8; j++) b[j] = Bs[k][tc * 8 + j];
#pragma unroll
            for (int i = 0; i < 4; i++)
#pragma unroll
                for (int j = 0; j < 8; j++)
                    acc[i][j] = fmaf(a[i], b[j], acc[i][j]);
        }
        __syncthreads();
    }

#pragma unroll
    for (int i = 0; i < 4; i++) {
        int gr = m0 + tr * 4 + i;
        if (gr >= N_NODES) continue;
        float dd = g_dis[gr];
        float sn = dd * dd;  // self-loop norm = 1/(deg+1)
        float* xwrow = g_xw + (size_t)gr * DIM + tc * 8;
        float* orow  = out  + (size_t)gr * DIM + tc * 8;
        float4 v0 = make_float4(acc[i][0], acc[i][1], acc[i][2], acc[i][3]);
        float4 v1 = make_float4(acc[i][4], acc[i][5], acc[i][6], acc[i][7]);
        *(float4*)(xwrow)     = v0;
        *(float4*)(xwrow + 4) = v1;
        float4 s0 = make_float4(v0.x * sn, v0.y * sn, v0.z * sn, v0.w * sn);
        float4 s1 = make_float4(v1.x * sn, v1.y * sn, v1.z * sn, v1.w * sn);
        *(float4*)(orow)      = s0;
        *(float4*)(orow + 4)  = s1;
    }
}

// ---------------- edge scatter: one warp per edge ----------------
__global__ __launch_bounds__(256) void k_scatter(float* __restrict__ out) {
    int w    = (blockIdx.x * blockDim.x + threadIdx.x) >> 5;
    int lane = threadIdx.x & 31;
    if (w >= N_EDGES) return;
    int r = g_row[w];   // source
    int c = g_col[w];   // target
    float norm = g_dis[r] * g_dis[c];
    const float4* src = (const float4*)(g_xw + (size_t)r * DIM);
    float4 v = __ldg(&src[lane]);             // 32 lanes x float4 = 128 floats
    v.x *= norm; v.y *= norm; v.z *= norm; v.w *= norm;
    float* dst = out + (size_t)c * DIM + lane * 4;
    asm volatile("red.global.add.v4.f32 [%0], {%1,%2,%3,%4};"
                 :: "l"(dst), "f"(v.x), "f"(v.y), "f"(v.z), "f"(v.w)
                 : "memory");
}

// ---------------- bias + relu ----------------
__global__ void k_finish(const float* __restrict__ b, float* __restrict__ out) {
    int i = blockIdx.x * blockDim.x + threadIdx.x;
    if (i < N_NODES * (DIM / 4)) {
        float4 v = ((float4*)out)[i];
        float4 bb = ((const float4*)b)[i & 31];  // 128 floats = 32 float4 per row
        v.x = fmaxf(v.x + bb.x, 0.f);
        v.y = fmaxf(v.y + bb.y, 0.f);
        v.z = fmaxf(v.z + bb.z, 0.f);
        v.w = fmaxf(v.w + bb.w, 0.f);
        ((float4*)out)[i] = v;
    }
}

extern "C" void kernel_launch(void* const* d_in, const int* in_sizes, int n_in,
                              void* d_out, int out_size) {
    // Identify inputs by element count (robust to metadata ordering):
    //   x: 12,800,000   edge_index: 3,200,000   W: 16,384   b: 128
    const float* x  = nullptr;
    const void*  ei = nullptr;
    const float* W  = nullptr;
    const float* b  = nullptr;
    for (int i = 0; i < n_in; i++) {
        switch (in_sizes[i]) {
            case 12800000: x  = (const float*)d_in[i]; break;
            case 3200000:  ei = d_in[i];               break;
            case 16384:    W  = (const float*)d_in[i]; break;
            case 128:      b  = (const float*)d_in[i]; break;
            default: break;
        }
    }
    float* out = (float*)d_out;
    const int* ei32 = (const int*)ei;

    k_zero_flag<<<1, 1>>>();
    k_detect<<<512, 256>>>(ei32);
    k_convert<<<(N_EDGES + 255) / 256, 256>>>(ei32);

    k_zero_deg<<<(N_NODES + 255) / 256, 256>>>();
    k_hist<<<(N_EDGES + 255) / 256, 256>>>();
    k_dis<<<(N_NODES + 255) / 256, 256>>>();

    k_gemm<<<(N_NODES + 63) / 64, 256>>>(x, W, out);

    {
        long long total_threads = (long long)N_EDGES * 32;
        int blocks = (int)((total_threads + 255) / 256);
        k_scatter<<<blocks, 256>>>(out);
    }
    k_finish<<<(N_NODES * (DIM / 4) + 255) / 256, 256>>>(b, out);
}

// round 3
// speedup vs baseline: 1.5049x; 1.5049x over previous
#include <cuda_runtime.h>

#define N_NODES 100000
#define N_EDGES 1600000
#define DIM 128
#define NB_SCAN 391   // ceil(100000/256)

// Scratch (allocation-free rule: __device__ globals)
__device__ float g_xw[(size_t)N_NODES * DIM];   // 51.2 MB
__device__ float g_dis[N_NODES];
__device__ int   g_deg[N_NODES];
__device__ int   g_off[N_NODES];     // exclusive prefix of deg
__device__ int   g_cur[N_NODES];     // placement cursors
__device__ int   g_erow[N_EDGES];    // edge source, sorted by target
__device__ int   g_row[N_EDGES];
__device__ int   g_col[N_EDGES];
__device__ int   g_bsum[NB_SCAN];
__device__ int   g_boff[NB_SCAN];
__device__ int   g_orflag;           // OR of odd int32 words; 0 => edge_index is int64

// ---------------- dtype detect + convert ----------------
__global__ void k_zero_flag() { g_orflag = 0; }

__global__ void k_detect(const int* __restrict__ ei32) {
    int i = blockIdx.x * blockDim.x + threadIdx.x;
    int acc = 0;
    for (int j = i; j < N_EDGES; j += gridDim.x * blockDim.x)
        acc |= ei32[2 * j + 1];
    if (acc != 0) atomicOr(&g_orflag, 1);
}

__global__ void k_convert(const int* __restrict__ ei32) {
    int e = blockIdx.x * blockDim.x + threadIdx.x;
    if (e >= N_EDGES) return;
    if (g_orflag == 0) {  // int64 layout: take low words
        g_row[e] = ei32[2 * e];
        g_col[e] = ei32[2 * (N_EDGES + e)];
    } else {              // int32 layout
        g_row[e] = ei32[e];
        g_col[e] = ei32[N_EDGES + e];
    }
}

// ---------------- degree / norm ----------------
__global__ void k_zero_deg() {
    int i = blockIdx.x * blockDim.x + threadIdx.x;
    if (i < N_NODES) g_deg[i] = 0;
}

__global__ void k_hist() {
    int e = blockIdx.x * blockDim.x + threadIdx.x;
    if (e < N_EDGES) atomicAdd(&g_deg[g_col[e]], 1);
}

__global__ void k_dis() {
    int i = blockIdx.x * blockDim.x + threadIdx.x;
    if (i < N_NODES) g_dis[i] = rsqrtf((float)(g_deg[i] + 1)); // +1 self loop
}

// ---------------- exclusive scan of g_deg -> g_off (3 kernels) ----------------
__global__ __launch_bounds__(256) void k_scan1() {
    __shared__ int s[256];
    int t = threadIdx.x;
    int i = blockIdx.x * 256 + t;
    int v = (i < N_NODES) ? g_deg[i] : 0;
    s[t] = v; __syncthreads();
#pragma unroll
    for (int off = 1; off < 256; off <<= 1) {
        int tmp = (t >= off) ? s[t - off] : 0;
        __syncthreads();
        s[t] += tmp;
        __syncthreads();
    }
    if (i < N_NODES) g_off[i] = s[t] - v;         // block-local exclusive
    if (t == 255) g_bsum[blockIdx.x] = s[255];
}

__global__ __launch_bounds__(512) void k_scan2() {
    __shared__ int s[512];
    int t = threadIdx.x;
    int v = (t < NB_SCAN) ? g_bsum[t] : 0;
    s[t] = v; __syncthreads();
#pragma unroll
    for (int off = 1; off < 512; off <<= 1) {
        int tmp = (t >= off) ? s[t - off] : 0;
        __syncthreads();
        s[t] += tmp;
        __syncthreads();
    }
    if (t < NB_SCAN) g_boff[t] = s[t] - v;        // exclusive
}

__global__ __launch_bounds__(256) void k_scan3() {
    int i = blockIdx.x * 256 + threadIdx.x;
    if (i < N_NODES) {
        int o = g_off[i] + g_boff[blockIdx.x];
        g_off[i] = o;
        g_cur[i] = o;
    }
}

// ---------------- place edges into CSR buckets ----------------
__global__ void k_place() {
    int e = blockIdx.x * blockDim.x + threadIdx.x;
    if (e >= N_EDGES) return;
    int c = g_col[e];
    int pos = atomicAdd(&g_cur[c], 1);
    g_erow[pos] = g_row[e];
}

// ---------------- GEMM: g_xw = x @ W ----------------
// BM=64, BN=128 (full), BK=32. 256 threads, per-thread 4x8 microtile.
__global__ __launch_bounds__(256) void k_gemm(const float* __restrict__ x,
                                              const float* __restrict__ W) {
    __shared__ float As[64][33];
    __shared__ float Bs[32][128];
    const int m0  = blockIdx.x * 64;
    const int tid = threadIdx.x;
    const int tr  = tid >> 4;
    const int tc  = tid & 15;

    float acc[4][8];
#pragma unroll
    for (int i = 0; i < 4; i++)
#pragma unroll
        for (int j = 0; j < 8; j++) acc[i][j] = 0.f;

    for (int kt = 0; kt < DIM; kt += 32) {
#pragma unroll
        for (int i = 0; i < 8; i++) {
            int idx = tid + i * 256;
            int r = idx >> 5, c = idx & 31;
            int gr = m0 + r;
            As[r][c] = (gr < N_NODES) ? x[(size_t)gr * DIM + kt + c] : 0.f;
        }
#pragma unroll
        for (int i = 0; i < 16; i++) {
            int idx = tid + i * 256;
            int r = idx >> 7, c = idx & 127;
            Bs[r][c] = W[(kt + r) * DIM + c];
        }
        __syncthreads();
#pragma unroll
        for (int k = 0; k < 32; k++) {
            float a[4], b[8];
#pragma unroll
            for (int i = 0; i < 4; i++) a[i] = As[tr * 4 + i][k];
#pragma unroll
            for (int j = 0; j < 8; j++) b[j] = Bs[k][tc * 8 + j];
#pragma unroll
            for (int i = 0; i < 4; i++)
#pragma unroll
                for (int j = 0; j < 8; j++)
                    acc[i][j] = fmaf(a[i], b[j], acc[i][j]);
        }
        __syncthreads();
    }

#pragma unroll
    for (int i = 0; i < 4; i++) {
        int gr = m0 + tr * 4 + i;
        if (gr >= N_NODES) continue;
        float* xwrow = g_xw + (size_t)gr * DIM + tc * 8;
        *(float4*)(xwrow)     = make_float4(acc[i][0], acc[i][1], acc[i][2], acc[i][3]);
        *(float4*)(xwrow + 4) = make_float4(acc[i][4], acc[i][5], acc[i][6], acc[i][7]);
    }
}

// ---------------- CSR gather: one warp per node, fused self-loop+bias+relu ----------------
__global__ __launch_bounds__(256) void k_gather(const float* __restrict__ b,
                                                float* __restrict__ out) {
    int n    = (blockIdx.x * blockDim.x + threadIdx.x) >> 5;
    int lane = threadIdx.x & 31;
    if (n >= N_NODES) return;

    const float4* xw4 = (const float4*)g_xw;
    float dn = g_dis[n];

    // self-loop: norm = dis[n]^2
    float4 v = __ldg(&xw4[(size_t)n * 32 + lane]);
    float sn = dn * dn;
    float4 acc = make_float4(v.x * sn, v.y * sn, v.z * sn, v.w * sn);

    int beg = g_off[n];
    int end = (n + 1 < N_NODES) ? g_off[n + 1] : N_EDGES;

    int e = beg;
    for (; e + 1 < end; e += 2) {
        int r0 = g_erow[e];
        int r1 = g_erow[e + 1];
        float w0 = g_dis[r0] * dn;
        float w1 = g_dis[r1] * dn;
        float4 v0 = __ldg(&xw4[(size_t)r0 * 32 + lane]);
        float4 v1 = __ldg(&xw4[(size_t)r1 * 32 + lane]);
        acc.x += v0.x * w0 + v1.x * w1;
        acc.y += v0.y * w0 + v1.y * w1;
        acc.z += v0.z * w0 + v1.z * w1;
        acc.w += v0.w * w0 + v1.w * w1;
    }
    if (e < end) {
        int r0 = g_erow[e];
        float w0 = g_dis[r0] * dn;
        float4 v0 = __ldg(&xw4[(size_t)r0 * 32 + lane]);
        acc.x += v0.x * w0; acc.y += v0.y * w0;
        acc.z += v0.z * w0; acc.w += v0.w * w0;
    }

    float4 bb = ((const float4*)b)[lane];
    acc.x = fmaxf(acc.x + bb.x, 0.f);
    acc.y = fmaxf(acc.y + bb.y, 0.f);
    acc.z = fmaxf(acc.z + bb.z, 0.f);
    acc.w = fmaxf(acc.w + bb.w, 0.f);
    ((float4*)out)[(size_t)n * 32 + lane] = acc;
}

extern "C" void kernel_launch(void* const* d_in, const int* in_sizes, int n_in,
                              void* d_out, int out_size) {
    // Identify inputs by element count:
    //   x: 12,800,000   edge_index: 3,200,000   W: 16,384   b: 128
    const float* x  = nullptr;
    const void*  ei = nullptr;
    const float* W  = nullptr;
    const float* b  = nullptr;
    for (int i = 0; i < n_in; i++) {
        switch (in_sizes[i]) {
            case 12800000: x  = (const float*)d_in[i]; break;
            case 3200000:  ei = d_in[i];               break;
            case 16384:    W  = (const float*)d_in[i]; break;
            case 128:      b  = (const float*)d_in[i]; break;
            default: break;
        }
    }
    float* out = (float*)d_out;
    const int* ei32 = (const int*)ei;

    k_zero_flag<<<1, 1>>>();
    k_detect<<<512, 256>>>(ei32);
    k_convert<<<(N_EDGES + 255) / 256, 256>>>(ei32);

    k_zero_deg<<<(N_NODES + 255) / 256, 256>>>();
    k_hist<<<(N_EDGES + 255) / 256, 256>>>();
    k_dis<<<(N_NODES + 255) / 256, 256>>>();

    k_scan1<<<NB_SCAN, 256>>>();
    k_scan2<<<1, 512>>>();
    k_scan3<<<NB_SCAN, 256>>>();
    k_place<<<(N_EDGES + 255) / 256, 256>>>();

    k_gemm<<<(N_NODES + 63) / 64, 256>>>(x, W);

    {
        long long total_threads = (long long)N_NODES * 32;
        int blocks = (int)((total_threads + 255) / 256);
        k_gather<<<blocks, 256>>>(b, out);
    }
}

// round 4
// speedup vs baseline: 2.3492x; 1.5610x over previous
#include <cuda_runtime.h>

#define N_NODES 100000
#define N_EDGES 1600000
#define DIM 128
#define NB_SCAN 391   // ceil(100000/256)

// Scratch (allocation-free rule: __device__ globals)
__device__ float g_xw[(size_t)N_NODES * DIM];   // 51.2 MB
__device__ float g_dis[N_NODES];
__device__ int   g_deg[N_NODES];
__device__ int   g_off[N_NODES];     // exclusive prefix of deg
__device__ int   g_cur[N_NODES];     // placement cursors
__device__ int   g_erow[N_EDGES];    // edge source, sorted by target
__device__ int   g_row[N_EDGES];
__device__ int   g_col[N_EDGES];
__device__ int   g_bsum[NB_SCAN];
__device__ int   g_boff[NB_SCAN];
__device__ int   g_orflag;           // OR of odd int32 words; 0 => edge_index is int64

// ---------------- dtype detect ----------------
__global__ void k_zero_flag() { g_orflag = 0; }

__global__ void k_detect(const int* __restrict__ ei32) {
    int i = blockIdx.x * blockDim.x + threadIdx.x;
    int acc = 0;
    for (int j = i; j < N_EDGES; j += gridDim.x * blockDim.x)
        acc |= ei32[2 * j + 1];
    if (acc != 0) atomicOr(&g_orflag, 1);
}

__global__ void k_zero_deg() {
    int i = blockIdx.x * blockDim.x + threadIdx.x;
    if (i < N_NODES) g_deg[i] = 0;
}

// ---------------- fused convert + degree histogram ----------------
__global__ void k_convert_hist(const int* __restrict__ ei32) {
    int e = blockIdx.x * blockDim.x + threadIdx.x;
    if (e >= N_EDGES) return;
    int r, c;
    if (g_orflag == 0) {  // int64 layout: take low words
        r = ei32[2 * e];
        c = ei32[2 * (N_EDGES + e)];
    } else {              // int32 layout
        r = ei32[e];
        c = ei32[N_EDGES + e];
    }
    g_row[e] = r;
    g_col[e] = c;
    atomicAdd(&g_deg[c], 1);
}

__global__ void k_dis() {
    int i = blockIdx.x * blockDim.x + threadIdx.x;
    if (i < N_NODES) g_dis[i] = rsqrtf((float)(g_deg[i] + 1)); // +1 self loop
}

// ---------------- exclusive scan of g_deg -> g_off (3 kernels) ----------------
__global__ __launch_bounds__(256) void k_scan1() {
    __shared__ int s[256];
    int t = threadIdx.x;
    int i = blockIdx.x * 256 + t;
    int v = (i < N_NODES) ? g_deg[i] : 0;
    s[t] = v; __syncthreads();
#pragma unroll
    for (int off = 1; off < 256; off <<= 1) {
        int tmp = (t >= off) ? s[t - off] : 0;
        __syncthreads();
        s[t] += tmp;
        __syncthreads();
    }
    if (i < N_NODES) g_off[i] = s[t] - v;
    if (t == 255) g_bsum[blockIdx.x] = s[255];
}

__global__ __launch_bounds__(512) void k_scan2() {
    __shared__ int s[512];
    int t = threadIdx.x;
    int v = (t < NB_SCAN) ? g_bsum[t] : 0;
    s[t] = v; __syncthreads();
#pragma unroll
    for (int off = 1; off < 512; off <<= 1) {
        int tmp = (t >= off) ? s[t - off] : 0;
        __syncthreads();
        s[t] += tmp;
        __syncthreads();
    }
    if (t < NB_SCAN) g_boff[t] = s[t] - v;
}

__global__ __launch_bounds__(256) void k_scan3() {
    int i = blockIdx.x * 256 + threadIdx.x;
    if (i < N_NODES) {
        int o = g_off[i] + g_boff[blockIdx.x];
        g_off[i] = o;
        g_cur[i] = o;
    }
}

// ---------------- place edges into CSR buckets ----------------
__global__ void k_place() {
    int e = blockIdx.x * blockDim.x + threadIdx.x;
    if (e >= N_EDGES) return;
    int c = g_col[e];
    int pos = atomicAdd(&g_cur[c], 1);
    g_erow[pos] = g_row[e];
}

// ---------------- tf32 tensor-core GEMM: g_xw = x @ W ----------------
// BM=128, BN=128 (full N), BK=32, 4 K-iters. 256 threads = 8 warps (4x2),
// warp tile 32x64 = 2 (m16) x 8 (n8) mma.sync.m16n8k8 tiles.
// Smem pads chosen conflict-free: A[.][36] -> frag bank = 4r+c (distinct),
// B[.][136] -> frag bank = 8k+q (distinct). STS also conflict-free.
__global__ __launch_bounds__(256) void k_gemm(const float* __restrict__ x,
                                              const float* __restrict__ W) {
    __shared__ unsigned As[128][36];
    __shared__ unsigned Bs[32][136];
    const int m0   = blockIdx.x * 128;
    const int tid  = threadIdx.x;
    const int warp = tid >> 5;
    const int lane = tid & 31;
    const int wm   = warp >> 1;   // 0..3
    const int wn   = warp & 1;    // 0..1
    const int qr   = lane >> 2;   // 0..7
    const int qc   = lane & 3;    // 0..3

    float acc[2][8][4];
#pragma unroll
    for (int mi = 0; mi < 2; mi++)
#pragma unroll
        for (int ni = 0; ni < 8; ni++)
#pragma unroll
            for (int j = 0; j < 4; j++) acc[mi][ni][j] = 0.f;

#pragma unroll 1
    for (int kt = 0; kt < 4; kt++) {
        // load A tile 128x32 (16 floats/thread, coalesced), convert to tf32
#pragma unroll
        for (int i = 0; i < 16; i++) {
            int idx = tid + i * 256;
            int r = idx >> 5, c = idx & 31;
            int gr = m0 + r;
            float v = (gr < N_NODES) ? __ldg(&x[(size_t)gr * DIM + kt * 32 + c]) : 0.f;
            unsigned u;
            asm("cvt.rna.tf32.f32 %0, %1;" : "=r"(u) : "f"(v));
            As[r][c] = u;
        }
        // load B tile 32x128 (16 floats/thread, coalesced), convert to tf32
#pragma unroll
        for (int i = 0; i < 16; i++) {
            int idx = tid + i * 256;
            int r = idx >> 7, c = idx & 127;
            float v = __ldg(&W[(kt * 32 + r) * DIM + c]);
            unsigned u;
            asm("cvt.rna.tf32.f32 %0, %1;" : "=r"(u) : "f"(v));
            Bs[r][c] = u;
        }
        __syncthreads();

#pragma unroll
        for (int ks = 0; ks < 4; ks++) {
            const int k0 = ks * 8;
            unsigned a[2][4], bf[8][2];
#pragma unroll
            for (int mi = 0; mi < 2; mi++) {
                int rb = wm * 32 + mi * 16;
                a[mi][0] = As[rb + qr][k0 + qc];
                a[mi][1] = As[rb + qr + 8][k0 + qc];
                a[mi][2] = As[rb + qr][k0 + qc + 4];
                a[mi][3] = As[rb + qr + 8][k0 + qc + 4];
            }
#pragma unroll
            for (int ni = 0; ni < 8; ni++) {
                int cb = wn * 64 + ni * 8;
                bf[ni][0] = Bs[k0 + qc][cb + qr];
                bf[ni][1] = Bs[k0 + qc + 4][cb + qr];
            }
#pragma unroll
            for (int mi = 0; mi < 2; mi++)
#pragma unroll
                for (int ni = 0; ni < 8; ni++) {
                    asm volatile(
                        "mma.sync.aligned.m16n8k8.row.col.f32.tf32.tf32.f32 "
                        "{%0,%1,%2,%3}, {%4,%5,%6,%7}, {%8,%9}, {%0,%1,%2,%3};"
                        : "+f"(acc[mi][ni][0]), "+f"(acc[mi][ni][1]),
                          "+f"(acc[mi][ni][2]), "+f"(acc[mi][ni][3])
                        : "r"(a[mi][0]), "r"(a[mi][1]), "r"(a[mi][2]), "r"(a[mi][3]),
                          "r"(bf[ni][0]), "r"(bf[ni][1]));
                }
        }
        __syncthreads();
    }

    // epilogue: C frag c0/c1 at (qr, 2qc), c2/c3 at (qr+8, 2qc)
#pragma unroll
    for (int mi = 0; mi < 2; mi++) {
        int r0 = m0 + wm * 32 + mi * 16 + qr;
        int r1 = r0 + 8;
#pragma unroll
        for (int ni = 0; ni < 8; ni++) {
            int cb = wn * 64 + ni * 8 + qc * 2;
            if (r0 < N_NODES)
                *(float2*)&g_xw[(size_t)r0 * DIM + cb] =
                    make_float2(acc[mi][ni][0], acc[mi][ni][1]);
            if (r1 < N_NODES)
                *(float2*)&g_xw[(size_t)r1 * DIM + cb] =
                    make_float2(acc[mi][ni][2], acc[mi][ni][3]);
        }
    }
}

// ---------------- CSR gather: one warp per node, fused self-loop+bias+relu ----------------
__global__ __launch_bounds__(256) void k_gather(const float* __restrict__ b,
                                                float* __restrict__ out) {
    int n    = (blockIdx.x * blockDim.x + threadIdx.x) >> 5;
    int lane = threadIdx.x & 31;
    if (n >= N_NODES) return;

    const float4* xw4 = (const float4*)g_xw;
    float dn = g_dis[n];

    float4 v = __ldg(&xw4[(size_t)n * 32 + lane]);
    float sn = dn * dn;
    float4 acc = make_float4(v.x * sn, v.y * sn, v.z * sn, v.w * sn);

    int beg = g_off[n];
    int end = (n + 1 < N_NODES) ? g_off[n + 1] : N_EDGES;

    int e = beg;
    for (; e + 1 < end; e += 2) {
        int r0 = g_erow[e];
        int r1 = g_erow[e + 1];
        float w0 = g_dis[r0] * dn;
        float w1 = g_dis[r1] * dn;
        float4 v0 = __ldg(&xw4[(size_t)r0 * 32 + lane]);
        float4 v1 = __ldg(&xw4[(size_t)r1 * 32 + lane]);
        acc.x += v0.x * w0 + v1.x * w1;
        acc.y += v0.y * w0 + v1.y * w1;
        acc.z += v0.z * w0 + v1.z * w1;
        acc.w += v0.w * w0 + v1.w * w1;
    }
    if (e < end) {
        int r0 = g_erow[e];
        float w0 = g_dis[r0] * dn;
        float4 v0 = __ldg(&xw4[(size_t)r0 * 32 + lane]);
        acc.x += v0.x * w0; acc.y += v0.y * w0;
        acc.z += v0.z * w0; acc.w += v0.w * w0;
    }

    float4 bb = ((const float4*)b)[lane];
    acc.x = fmaxf(acc.x + bb.x, 0.f);
    acc.y = fmaxf(acc.y + bb.y, 0.f);
    acc.z = fmaxf(acc.z + bb.z, 0.f);
    acc.w = fmaxf(acc.w + bb.w, 0.f);
    ((float4*)out)[(size_t)n * 32 + lane] = acc;
}

extern "C" void kernel_launch(void* const* d_in, const int* in_sizes, int n_in,
                              void* d_out, int out_size) {
    // Identify inputs by element count:
    //   x: 12,800,000   edge_index: 3,200,000   W: 16,384   b: 128
    const float* x  = nullptr;
    const void*  ei = nullptr;
    const float* W  = nullptr;
    const float* b  = nullptr;
    for (int i = 0; i < n_in; i++) {
        switch (in_sizes[i]) {
            case 12800000: x  = (const float*)d_in[i]; break;
            case 3200000:  ei = d_in[i];               break;
            case 16384:    W  = (const float*)d_in[i]; break;
            case 128:      b  = (const float*)d_in[i]; break;
            default: break;
        }
    }
    float* out = (float*)d_out;
    const int* ei32 = (const int*)ei;

    k_zero_flag<<<1, 1>>>();
    k_detect<<<512, 256>>>(ei32);
    k_zero_deg<<<(N_NODES + 255) / 256, 256>>>();
    k_convert_hist<<<(N_EDGES + 255) / 256, 256>>>(ei32);
    k_dis<<<(N_NODES + 255) / 256, 256>>>();

    k_scan1<<<NB_SCAN, 256>>>();
    k_scan2<<<1, 512>>>();
    k_scan3<<<NB_SCAN, 256>>>();
    k_place<<<(N_EDGES + 255) / 256, 256>>>();

    k_gemm<<<(N_NODES + 127) / 128, 256>>>(x, W);

    {
        long long total_threads = (long long)N_NODES * 32;
        int blocks = (int)((total_threads + 255) / 256);
        k_gather<<<blocks, 256>>>(b, out);
    }
}

// round 5
// speedup vs baseline: 2.5677x; 1.0930x over previous
#include <cuda_runtime.h>
#include <cuda_fp16.h>

#define N_NODES 100000
#define N_EDGES 1600000
#define DIM 128
#define NB_SCAN 391   // ceil(100000/256)

// Scratch (allocation-free rule: __device__ globals)
__device__ __half g_xw[(size_t)N_NODES * DIM];  // 25.6 MB, fp16
__device__ float g_dis[N_NODES];
__device__ int   g_deg[N_NODES];
__device__ int   g_off[N_NODES];     // exclusive prefix of deg
__device__ int   g_cur[N_NODES];     // placement cursors
__device__ int   g_erow[N_EDGES];    // edge source, sorted by target
__device__ int   g_row[N_EDGES];
__device__ int   g_col[N_EDGES];
__device__ int   g_bsum[NB_SCAN];
__device__ int   g_boff[NB_SCAN];
__device__ int   g_orflag;           // OR of sampled odd int32 words; 0 => int64

// ---------------- zero counters + flag ----------------
__global__ void k_init() {
    int i = blockIdx.x * blockDim.x + threadIdx.x;
    if (i < N_NODES) g_deg[i] = 0;
    if (i == 0) g_orflag = 0;
}

// ---------------- dtype detect (sampled: 8192 odd words, 1 block) ----------------
__global__ void k_detect(const int* __restrict__ ei32) {
    int t = threadIdx.x;
    int acc = 0;
    // 32 strided samples per thread across the first half of the buffer
#pragma unroll
    for (int s = 0; s < 32; s++) {
        int j = t + s * 256;                  // 0..8191
        long long idx = (long long)j * 195;   // spread over ~1.6M entries
        acc |= ei32[2 * idx + 1];
    }
    if (acc != 0) atomicOr(&g_orflag, 1);
}

// ---------------- fused convert + degree histogram ----------------
__global__ void k_convert_hist(const int* __restrict__ ei32) {
    int e = blockIdx.x * blockDim.x + threadIdx.x;
    if (e >= N_EDGES) return;
    int r, c;
    if (g_orflag == 0) {  // int64 layout: take low words
        r = ei32[2 * e];
        c = ei32[2 * (N_EDGES + e)];
    } else {              // int32 layout
        r = ei32[e];
        c = ei32[N_EDGES + e];
    }
    g_row[e] = r;
    g_col[e] = c;
    atomicAdd(&g_deg[c], 1);
}

// ---------------- scan1 (fused: also computes g_dis) ----------------
__global__ __launch_bounds__(256) void k_scan1() {
    __shared__ int s[256];
    int t = threadIdx.x;
    int i = blockIdx.x * 256 + t;
    int v = (i < N_NODES) ? g_deg[i] : 0;
    if (i < N_NODES) g_dis[i] = rsqrtf((float)(v + 1)); // +1 self loop
    s[t] = v; __syncthreads();
#pragma unroll
    for (int off = 1; off < 256; off <<= 1) {
        int tmp = (t >= off) ? s[t - off] : 0;
        __syncthreads();
        s[t] += tmp;
        __syncthreads();
    }
    if (i < N_NODES) g_off[i] = s[t] - v;
    if (t == 255) g_bsum[blockIdx.x] = s[255];
}

__global__ __launch_bounds__(512) void k_scan2() {
    __shared__ int s[512];
    int t = threadIdx.x;
    int v = (t < NB_SCAN) ? g_bsum[t] : 0;
    s[t] = v; __syncthreads();
#pragma unroll
    for (int off = 1; off < 512; off <<= 1) {
        int tmp = (t >= off) ? s[t - off] : 0;
        __syncthreads();
        s[t] += tmp;
        __syncthreads();
    }
    if (t < NB_SCAN) g_boff[t] = s[t] - v;
}

__global__ __launch_bounds__(256) void k_scan3() {
    int i = blockIdx.x * 256 + threadIdx.x;
    if (i < N_NODES) {
        int o = g_off[i] + g_boff[blockIdx.x];
        g_off[i] = o;
        g_cur[i] = o;
    }
}

// ---------------- place edges into CSR buckets ----------------
__global__ void k_place() {
    int e = blockIdx.x * blockDim.x + threadIdx.x;
    if (e >= N_EDGES) return;
    int c = g_col[e];
    int pos = atomicAdd(&g_cur[c], 1);
    g_erow[pos] = g_row[e];
}

// ---------------- tf32 tensor-core GEMM: g_xw = fp16(x @ W) ----------------
// BM=128, BN=128 (full N), BK=32, 4 K-iters. 256 threads = 8 warps (4x2),
// warp tile 32x64 = 2 (m16) x 8 (n8) mma.sync.m16n8k8 tiles.
__global__ __launch_bounds__(256) void k_gemm(const float* __restrict__ x,
                                              const float* __restrict__ W) {
    __shared__ unsigned As[128][36];
    __shared__ unsigned Bs[32][136];
    const int m0   = blockIdx.x * 128;
    const int tid  = threadIdx.x;
    const int warp = tid >> 5;
    const int lane = tid & 31;
    const int wm   = warp >> 1;   // 0..3
    const int wn   = warp & 1;    // 0..1
    const int qr   = lane >> 2;   // 0..7
    const int qc   = lane & 3;    // 0..3

    float acc[2][8][4];
#pragma unroll
    for (int mi = 0; mi < 2; mi++)
#pragma unroll
        for (int ni = 0; ni < 8; ni++)
#pragma unroll
            for (int j = 0; j < 4; j++) acc[mi][ni][j] = 0.f;

#pragma unroll 1
    for (int kt = 0; kt < 4; kt++) {
#pragma unroll
        for (int i = 0; i < 16; i++) {
            int idx = tid + i * 256;
            int r = idx >> 5, c = idx & 31;
            int gr = m0 + r;
            float v = (gr < N_NODES) ? __ldg(&x[(size_t)gr * DIM + kt * 32 + c]) : 0.f;
            unsigned u;
            asm("cvt.rna.tf32.f32 %0, %1;" : "=r"(u) : "f"(v));
            As[r][c] = u;
        }
#pragma unroll
        for (int i = 0; i < 16; i++) {
            int idx = tid + i * 256;
            int r = idx >> 7, c = idx & 127;
            float v = __ldg(&W[(kt * 32 + r) * DIM + c]);
            unsigned u;
            asm("cvt.rna.tf32.f32 %0, %1;" : "=r"(u) : "f"(v));
            Bs[r][c] = u;
        }
        __syncthreads();

#pragma unroll
        for (int ks = 0; ks < 4; ks++) {
            const int k0 = ks * 8;
            unsigned a[2][4], bf[8][2];
#pragma unroll
            for (int mi = 0; mi < 2; mi++) {
                int rb = wm * 32 + mi * 16;
                a[mi][0] = As[rb + qr][k0 + qc];
                a[mi][1] = As[rb + qr + 8][k0 + qc];
                a[mi][2] = As[rb + qr][k0 + qc + 4];
                a[mi][3] = As[rb + qr + 8][k0 + qc + 4];
            }
#pragma unroll
            for (int ni = 0; ni < 8; ni++) {
                int cb = wn * 64 + ni * 8;
                bf[ni][0] = Bs[k0 + qc][cb + qr];
                bf[ni][1] = Bs[k0 + qc + 4][cb + qr];
            }
#pragma unroll
            for (int mi = 0; mi < 2; mi++)
#pragma unroll
                for (int ni = 0; ni < 8; ni++) {
                    asm volatile(
                        "mma.sync.aligned.m16n8k8.row.col.f32.tf32.tf32.f32 "
                        "{%0,%1,%2,%3}, {%4,%5,%6,%7}, {%8,%9}, {%0,%1,%2,%3};"
                        : "+f"(acc[mi][ni][0]), "+f"(acc[mi][ni][1]),
                          "+f"(acc[mi][ni][2]), "+f"(acc[mi][ni][3])
                        : "r"(a[mi][0]), "r"(a[mi][1]), "r"(a[mi][2]), "r"(a[mi][3]),
                          "r"(bf[ni][0]), "r"(bf[ni][1]));
                }
        }
        __syncthreads();
    }

    // epilogue: C frag c0/c1 at (qr, 2qc), c2/c3 at (qr+8, 2qc); pack fp16x2
#pragma unroll
    for (int mi = 0; mi < 2; mi++) {
        int r0 = m0 + wm * 32 + mi * 16 + qr;
        int r1 = r0 + 8;
#pragma unroll
        for (int ni = 0; ni < 8; ni++) {
            int cb = wn * 64 + ni * 8 + qc * 2;
            if (r0 < N_NODES)
                *(__half2*)&g_xw[(size_t)r0 * DIM + cb] =
                    __floats2half2_rn(acc[mi][ni][0], acc[mi][ni][1]);
            if (r1 < N_NODES)
                *(__half2*)&g_xw[(size_t)r1 * DIM + cb] =
                    __floats2half2_rn(acc[mi][ni][2], acc[mi][ni][3]);
        }
    }
}

// ---------------- CSR gather (fp16 rows): warp/node, fused self-loop+bias+relu ----------------
__global__ __launch_bounds__(256) void k_gather(const float* __restrict__ b,
                                                float* __restrict__ out) {
    int n    = (blockIdx.x * blockDim.x + threadIdx.x) >> 5;
    int lane = threadIdx.x & 31;
    if (n >= N_NODES) return;

    const uint2* xw2 = (const uint2*)g_xw;  // 8 B per lane = 4 fp16 features
    float dn = g_dis[n];

    uint2 us = __ldg(&xw2[(size_t)n * 32 + lane]);
    float2 s0 = __half22float2(*(__half2*)&us.x);
    float2 s1 = __half22float2(*(__half2*)&us.y);
    float sn = dn * dn;
    float4 acc = make_float4(s0.x * sn, s0.y * sn, s1.x * sn, s1.y * sn);

    int beg = g_off[n];
    int end = (n + 1 < N_NODES) ? g_off[n + 1] : N_EDGES;

    int e = beg;
    for (; e + 1 < end; e += 2) {
        int r0 = g_erow[e];
        int r1 = g_erow[e + 1];
        float w0 = g_dis[r0] * dn;
        float w1 = g_dis[r1] * dn;
        uint2 u0 = __ldg(&xw2[(size_t)r0 * 32 + lane]);
        uint2 u1 = __ldg(&xw2[(size_t)r1 * 32 + lane]);
        float2 a0 = __half22float2(*(__half2*)&u0.x);
        float2 a1 = __half22float2(*(__half2*)&u0.y);
        float2 c0 = __half22float2(*(__half2*)&u1.x);
        float2 c1 = __half22float2(*(__half2*)&u1.y);
        acc.x += a0.x * w0 + c0.x * w1;
        acc.y += a0.y * w0 + c0.y * w1;
        acc.z += a1.x * w0 + c1.x * w1;
        acc.w += a1.y * w0 + c1.y * w1;
    }
    if (e < end) {
        int r0 = g_erow[e];
        float w0 = g_dis[r0] * dn;
        uint2 u0 = __ldg(&xw2[(size_t)r0 * 32 + lane]);
        float2 a0 = __half22float2(*(__half2*)&u0.x);
        float2 a1 = __half22float2(*(__half2*)&u0.y);
        acc.x += a0.x * w0; acc.y += a0.y * w0;
        acc.z += a1.x * w0; acc.w += a1.y * w0;
    }

    float4 bb = ((const float4*)b)[lane];
    acc.x = fmaxf(acc.x + bb.x, 0.f);
    acc.y = fmaxf(acc.y + bb.y, 0.f);
    acc.z = fmaxf(acc.z + bb.z, 0.f);
    acc.w = fmaxf(acc.w + bb.w, 0.f);
    ((float4*)out)[(size_t)n * 32 + lane] = acc;
}

extern "C" void kernel_launch(void* const* d_in, const int* in_sizes, int n_in,
                              void* d_out, int out_size) {
    // Identify inputs by element count:
    //   x: 12,800,000   edge_index: 3,200,000   W: 16,384   b: 128
    const float* x  = nullptr;
    const void*  ei = nullptr;
    const float* W  = nullptr;
    const float* b  = nullptr;
    for (int i = 0; i < n_in; i++) {
        switch (in_sizes[i]) {
            case 12800000: x  = (const float*)d_in[i]; break;
            case 3200000:  ei = d_in[i];               break;
            case 16384:    W  = (const float*)d_in[i]; break;
            case 128:      b  = (const float*)d_in[i]; break;
            default: break;
        }
    }
    float* out = (float*)d_out;
    const int* ei32 = (const int*)ei;

    k_init<<<(N_NODES + 255) / 256, 256>>>();
    k_detect<<<1, 256>>>(ei32);
    k_convert_hist<<<(N_EDGES + 255) / 256, 256>>>(ei32);

    k_scan1<<<NB_SCAN, 256>>>();
    k_scan2<<<1, 512>>>();
    k_scan3<<<NB_SCAN, 256>>>();
    k_place<<<(N_EDGES + 255) / 256, 256>>>();

    k_gemm<<<(N_NODES + 127) / 128, 256>>>(x, W);

    {
        long long total_threads = (long long)N_NODES * 32;
        int blocks = (int)((total_threads + 255) / 256);
        k_gather<<<blocks, 256>>>(b, out);
    }
}

// round 6
// speedup vs baseline: 2.7807x; 1.0829x over previous
#include <cuda_runtime.h>
#include <cuda_fp16.h>

#define N_NODES 100000
#define N_EDGES 1600000
#define DIM 128
#define NB_SCAN 391   // ceil(100000/256)

// Scratch (allocation-free rule: __device__ globals)
__device__ __half g_xw[(size_t)N_NODES * DIM];  // 25.6 MB, fp16
__device__ float g_dis[N_NODES];
__device__ int   g_deg[N_NODES];
__device__ int   g_off[N_NODES];     // exclusive prefix of deg
__device__ int   g_cur[N_NODES];     // placement cursors
__device__ int   g_erow[N_EDGES];    // edge source, sorted by target
__device__ int   g_bsum[NB_SCAN];
__device__ int   g_boff[NB_SCAN];
__device__ int   g_orflag;           // OR of sampled odd int32 words; 0 => int64

// ---------------- zero counters + flag ----------------
__global__ void k_init() {
    int i = blockIdx.x * blockDim.x + threadIdx.x;
    if (i < N_NODES) g_deg[i] = 0;
    if (i == 0) g_orflag = 0;
}

// ---------------- dtype detect (sampled: 8192 odd words, 1 block) ----------------
__global__ void k_detect(const int* __restrict__ ei32) {
    int t = threadIdx.x;
    int acc = 0;
#pragma unroll
    for (int s = 0; s < 32; s++) {
        int j = t + s * 256;                  // 0..8191
        long long idx = (long long)j * 195;   // spread over ~1.6M entries
        acc |= ei32[2 * idx + 1];
    }
    if (acc != 0) atomicOr(&g_orflag, 1);
}

// ---------------- degree histogram (decodes col half directly) ----------------
__global__ void k_hist(const int* __restrict__ ei32) {
    int e = blockIdx.x * blockDim.x + threadIdx.x;
    if (e >= N_EDGES) return;
    int c = (g_orflag == 0) ? ei32[2 * (N_EDGES + e)] : ei32[N_EDGES + e];
    atomicAdd(&g_deg[c], 1);
}

// ---------------- scan1 (fused: also computes g_dis) ----------------
__global__ __launch_bounds__(256) void k_scan1() {
    __shared__ int s[256];
    int t = threadIdx.x;
    int i = blockIdx.x * 256 + t;
    int v = (i < N_NODES) ? g_deg[i] : 0;
    if (i < N_NODES) g_dis[i] = rsqrtf((float)(v + 1)); // +1 self loop
    s[t] = v; __syncthreads();
#pragma unroll
    for (int off = 1; off < 256; off <<= 1) {
        int tmp = (t >= off) ? s[t - off] : 0;
        __syncthreads();
        s[t] += tmp;
        __syncthreads();
    }
    if (i < N_NODES) g_off[i] = s[t] - v;
    if (t == 255) g_bsum[blockIdx.x] = s[255];
}

__global__ __launch_bounds__(512) void k_scan2() {
    __shared__ int s[512];
    int t = threadIdx.x;
    int v = (t < NB_SCAN) ? g_bsum[t] : 0;
    s[t] = v; __syncthreads();
#pragma unroll
    for (int off = 1; off < 512; off <<= 1) {
        int tmp = (t >= off) ? s[t - off] : 0;
        __syncthreads();
        s[t] += tmp;
        __syncthreads();
    }
    if (t < NB_SCAN) g_boff[t] = s[t] - v;
}

__global__ __launch_bounds__(256) void k_scan3() {
    int i = blockIdx.x * 256 + threadIdx.x;
    if (i < N_NODES) {
        int o = g_off[i] + g_boff[blockIdx.x];
        g_off[i] = o;
        g_cur[i] = o;
    }
}

// ---------------- place edges into CSR buckets (re-decodes from ei32) ----------------
__global__ void k_place(const int* __restrict__ ei32) {
    int e = blockIdx.x * blockDim.x + threadIdx.x;
    if (e >= N_EDGES) return;
    int r, c;
    if (g_orflag == 0) {  // int64 layout: low words
        r = ei32[2 * e];
        c = ei32[2 * (N_EDGES + e)];
    } else {              // int32 layout
        r = ei32[e];
        c = ei32[N_EDGES + e];
    }
    int pos = atomicAdd(&g_cur[c], 1);
    g_erow[pos] = r;
}

// ---------------- tf32 tensor-core GEMM: g_xw = fp16(x @ W) ----------------
__global__ __launch_bounds__(256) void k_gemm(const float* __restrict__ x,
                                              const float* __restrict__ W) {
    __shared__ unsigned As[128][36];
    __shared__ unsigned Bs[32][136];
    const int m0   = blockIdx.x * 128;
    const int tid  = threadIdx.x;
    const int warp = tid >> 5;
    const int lane = tid & 31;
    const int wm   = warp >> 1;   // 0..3
    const int wn   = warp & 1;    // 0..1
    const int qr   = lane >> 2;   // 0..7
    const int qc   = lane & 3;    // 0..3

    float acc[2][8][4];
#pragma unroll
    for (int mi = 0; mi < 2; mi++)
#pragma unroll
        for (int ni = 0; ni < 8; ni++)
#pragma unroll
            for (int j = 0; j < 4; j++) acc[mi][ni][j] = 0.f;

#pragma unroll 1
    for (int kt = 0; kt < 4; kt++) {
#pragma unroll
        for (int i = 0; i < 16; i++) {
            int idx = tid + i * 256;
            int r = idx >> 5, c = idx & 31;
            int gr = m0 + r;
            float v = (gr < N_NODES) ? __ldg(&x[(size_t)gr * DIM + kt * 32 + c]) : 0.f;
            unsigned u;
            asm("cvt.rna.tf32.f32 %0, %1;" : "=r"(u) : "f"(v));
            As[r][c] = u;
        }
#pragma unroll
        for (int i = 0; i < 16; i++) {
            int idx = tid + i * 256;
            int r = idx >> 7, c = idx & 127;
            float v = __ldg(&W[(kt * 32 + r) * DIM + c]);
            unsigned u;
            asm("cvt.rna.tf32.f32 %0, %1;" : "=r"(u) : "f"(v));
            Bs[r][c] = u;
        }
        __syncthreads();

#pragma unroll
        for (int ks = 0; ks < 4; ks++) {
            const int k0 = ks * 8;
            unsigned a[2][4], bf[8][2];
#pragma unroll
            for (int mi = 0; mi < 2; mi++) {
                int rb = wm * 32 + mi * 16;
                a[mi][0] = As[rb + qr][k0 + qc];
                a[mi][1] = As[rb + qr + 8][k0 + qc];
                a[mi][2] = As[rb + qr][k0 + qc + 4];
                a[mi][3] = As[rb + qr + 8][k0 + qc + 4];
            }
#pragma unroll
            for (int ni = 0; ni < 8; ni++) {
                int cb = wn * 64 + ni * 8;
                bf[ni][0] = Bs[k0 + qc][cb + qr];
                bf[ni][1] = Bs[k0 + qc + 4][cb + qr];
            }
#pragma unroll
            for (int mi = 0; mi < 2; mi++)
#pragma unroll
                for (int ni = 0; ni < 8; ni++) {
                    asm volatile(
                        "mma.sync.aligned.m16n8k8.row.col.f32.tf32.tf32.f32 "
                        "{%0,%1,%2,%3}, {%4,%5,%6,%7}, {%8,%9}, {%0,%1,%2,%3};"
                        : "+f"(acc[mi][ni][0]), "+f"(acc[mi][ni][1]),
                          "+f"(acc[mi][ni][2]), "+f"(acc[mi][ni][3])
                        : "r"(a[mi][0]), "r"(a[mi][1]), "r"(a[mi][2]), "r"(a[mi][3]),
                          "r"(bf[ni][0]), "r"(bf[ni][1]));
                }
        }
        __syncthreads();
    }

#pragma unroll
    for (int mi = 0; mi < 2; mi++) {
        int r0 = m0 + wm * 32 + mi * 16 + qr;
        int r1 = r0 + 8;
#pragma unroll
        for (int ni = 0; ni < 8; ni++) {
            int cb = wn * 64 + ni * 8 + qc * 2;
            if (r0 < N_NODES)
                *(__half2*)&g_xw[(size_t)r0 * DIM + cb] =
                    __floats2half2_rn(acc[mi][ni][0], acc[mi][ni][1]);
            if (r1 < N_NODES)
                *(__half2*)&g_xw[(size_t)r1 * DIM + cb] =
                    __floats2half2_rn(acc[mi][ni][2], acc[mi][ni][3]);
        }
    }
}

// ---------------- CSR gather: warp/node, 4-edge unroll for MLP ----------------
__global__ __launch_bounds__(256) void k_gather(const float* __restrict__ b,
                                                float* __restrict__ out) {
    int n    = (blockIdx.x * blockDim.x + threadIdx.x) >> 5;
    int lane = threadIdx.x & 31;
    if (n >= N_NODES) return;

    const uint2* xw2 = (const uint2*)g_xw;  // 8 B per lane = 4 fp16 features
    float dn = g_dis[n];

    uint2 us = __ldg(&xw2[(size_t)n * 32 + lane]);
    float2 s0 = __half22float2(*(__half2*)&us.x);
    float2 s1 = __half22float2(*(__half2*)&us.y);
    float sn = dn * dn;
    float4 acc = make_float4(s0.x * sn, s0.y * sn, s1.x * sn, s1.y * sn);

    int beg = g_off[n];
    int end = (n + 1 < N_NODES) ? g_off[n + 1] : N_EDGES;

    int e = beg;
    // 4-wide: issue all index loads, then all weight loads, then all row loads
    for (; e + 3 < end; e += 4) {
        int r0 = __ldg(&g_erow[e]);
        int r1 = __ldg(&g_erow[e + 1]);
        int r2 = __ldg(&g_erow[e + 2]);
        int r3 = __ldg(&g_erow[e + 3]);
        float w0 = __ldg(&g_dis[r0]) * dn;
        float w1 = __ldg(&g_dis[r1]) * dn;
        float w2 = __ldg(&g_dis[r2]) * dn;
        float w3 = __ldg(&g_dis[r3]) * dn;
        uint2 u0 = __ldg(&xw2[(size_t)r0 * 32 + lane]);
        uint2 u1 = __ldg(&xw2[(size_t)r1 * 32 + lane]);
        uint2 u2 = __ldg(&xw2[(size_t)r2 * 32 + lane]);
        uint2 u3 = __ldg(&xw2[(size_t)r3 * 32 + lane]);
        float2 a0 = __half22float2(*(__half2*)&u0.x);
        float2 a1 = __half22float2(*(__half2*)&u0.y);
        float2 b0 = __half22float2(*(__half2*)&u1.x);
        float2 b1 = __half22float2(*(__half2*)&u1.y);
        float2 c0 = __half22float2(*(__half2*)&u2.x);
        float2 c1 = __half22float2(*(__half2*)&u2.y);
        float2 d0 = __half22float2(*(__half2*)&u3.x);
        float2 d1 = __half22float2(*(__half2*)&u3.y);
        acc.x += a0.x * w0 + b0.x * w1 + c0.x * w2 + d0.x * w3;
        acc.y += a0.y * w0 + b0.y * w1 + c0.y * w2 + d0.y * w3;
        acc.z += a1.x * w0 + b1.x * w1 + c1.x * w2 + d1.x * w3;
        acc.w += a1.y * w0 + b1.y * w1 + c1.y * w2 + d1.y * w3;
    }
    for (; e < end; e++) {
        int r0 = __ldg(&g_erow[e]);
        float w0 = __ldg(&g_dis[r0]) * dn;
        uint2 u0 = __ldg(&xw2[(size_t)r0 * 32 + lane]);
        float2 a0 = __half22float2(*(__half2*)&u0.x);
        float2 a1 = __half22float2(*(__half2*)&u0.y);
        acc.x += a0.x * w0; acc.y += a0.y * w0;
        acc.z += a1.x * w0; acc.w += a1.y * w0;
    }

    float4 bb = ((const float4*)b)[lane];
    acc.x = fmaxf(acc.x + bb.x, 0.f);
    acc.y = fmaxf(acc.y + bb.y, 0.f);
    acc.z = fmaxf(acc.z + bb.z, 0.f);
    acc.w = fmaxf(acc.w + bb.w, 0.f);
    ((float4*)out)[(size_t)n * 32 + lane] = acc;
}

extern "C" void kernel_launch(void* const* d_in, const int* in_sizes, int n_in,
                              void* d_out, int out_size) {
    // Identify inputs by element count:
    //   x: 12,800,000   edge_index: 3,200,000   W: 16,384   b: 128
    const float* x  = nullptr;
    const void*  ei = nullptr;
    const float* W  = nullptr;
    const float* b  = nullptr;
    for (int i = 0; i < n_in; i++) {
        switch (in_sizes[i]) {
            case 12800000: x  = (const float*)d_in[i]; break;
            case 3200000:  ei = d_in[i];               break;
            case 16384:    W  = (const float*)d_in[i]; break;
            case 128:      b  = (const float*)d_in[i]; break;
            default: break;
        }
    }
    float* out = (float*)d_out;
    const int* ei32 = (const int*)ei;

    // Fork: GEMM (depends only on x, W) runs on a side stream in parallel
    // with the edge-preprocessing chain; join before gather.
    // (Stream/event creation is host-side only — legal during capture; not
    //  destroyed to avoid touching objects that are part of the capture.)
    cudaStream_t s2;
    cudaStreamCreateWithFlags(&s2, cudaStreamNonBlocking);
    cudaEvent_t ev_fork, ev_join;
    cudaEventCreateWithFlags(&ev_fork, cudaEventDisableTiming);
    cudaEventCreateWithFlags(&ev_join, cudaEventDisableTiming);

    cudaEventRecord(ev_fork, 0);
    cudaStreamWaitEvent(s2, ev_fork, 0);
    k_gemm<<<(N_NODES + 127) / 128, 256, 0, s2>>>(x, W);
    cudaEventRecord(ev_join, s2);

    // main-stream preprocessing chain
    k_init<<<(N_NODES + 255) / 256, 256>>>();
    k_detect<<<1, 256>>>(ei32);
    k_hist<<<(N_EDGES + 255) / 256, 256>>>(ei32);
    k_scan1<<<NB_SCAN, 256>>>();
    k_scan2<<<1, 512>>>();
    k_scan3<<<NB_SCAN, 256>>>();
    k_place<<<(N_EDGES + 255) / 256, 256>>>(ei32);

    cudaStreamWaitEvent(0, ev_join, 0);
    {
        long long total_threads = (long long)N_NODES * 32;
        int blocks = (int)((total_threads + 255) / 256);
        k_gather<<<blocks, 256>>>(b, out);
    }
}